// round 3
// baseline (speedup 1.0000x reference)
#include <cuda_runtime.h>

#define BATCHSZ 2
#define DM      384
#define DI      768
#define LSEQ    1568
#define LTOT    3136
#define DTR     24
#define DST     16
#define DEPTH   24
#define NPATCH  3136
#define PKDIM   768

// ---------------- scratch ----------------
__device__ float g_patches[NPATCH * PKDIM];
__device__ float g_hidden [LTOT * DM];
__device__ float g_resid  [LTOT * DM];
__device__ float g_norm   [LTOT * DM];
__device__ float g_xzp    [2 * 2 * DI * LTOT];      // split-K partials of in_proj (e, bl)
__device__ float g_xc     [2 * DI * LTOT];          // (dir*DI+d, bl) scan order
__device__ float g_dt     [2 * DI * LTOT];
__device__ float g_xpart  [2 * 4 * 56 * LTOT];      // xproj split-K partials
__device__ float g_xdt24  [2 * 24 * LTOT];          // dt-rank rows of xdbl
__device__ float g_btr    [2 * BATCHSZ * LSEQ * DST];
__device__ float g_ctr    [2 * BATCHSZ * LSEQ * DST];
__device__ float g_ys     [2 * DI * LTOT];          // y' = ys + Dp*xc, bwd flipped
__device__ float g_ycomb  [DI * LTOT];

__global__ void k_zero(float* p, int n) {
    int i = blockIdx.x * blockDim.x + threadIdx.x;
    if (i < n) p[i] = 0.f;
}

__global__ void k_patch_gather(const float* __restrict__ x) {
    int idx = blockIdx.x * blockDim.x + threadIdx.x;
    if (idx >= NPATCH * PKDIM) return;
    int row = idx / PKDIM, c = idx % PKDIM;
    int b = row / 1568; int rem = row % 1568; int t = rem / 196; int n = rem % 196;
    int gy = n / 14, gx = n % 14;
    int ch = c / 256; int r = c % 256; int py = r / 16, px = r % 16;
    g_patches[idx] = x[(((long)(b * 3 + ch) * 8 + t) * 224 + gy * 16 + py) * 224 + gx * 16 + px];
}

// res += hidden; norm = rmsnorm(res)*nw
__global__ void k_prenorm(const float* __restrict__ nw) {
    int base = blockIdx.x * DM;
    __shared__ float red[4];
    float v[3]; float ss = 0.f;
#pragma unroll
    for (int i = 0; i < 3; i++) {
        int c = threadIdx.x + i * 128;
        float t = g_resid[base + c] + g_hidden[base + c];
        g_resid[base + c] = t; v[i] = t; ss += t * t;
    }
#pragma unroll
    for (int o = 16; o; o >>= 1) ss += __shfl_xor_sync(0xffffffffu, ss, o);
    if ((threadIdx.x & 31) == 0) red[threadIdx.x >> 5] = ss;
    __syncthreads();
    float r = rsqrtf((red[0] + red[1] + red[2] + red[3]) * (1.f / DM) + 1e-5f);
#pragma unroll
    for (int i = 0; i < 3; i++) {
        int c = threadIdx.x + i * 128;
        g_norm[base + c] = v[i] * r * nw[c];
    }
}

__global__ void k_final(const float* __restrict__ nf, float* __restrict__ out) {
    int base = blockIdx.x * DM;
    __shared__ float red[4];
    float v[3]; float ss = 0.f;
#pragma unroll
    for (int i = 0; i < 3; i++) {
        int c = threadIdx.x + i * 128;
        float t = g_resid[base + c] + g_hidden[base + c];
        v[i] = t; ss += t * t;
    }
#pragma unroll
    for (int o = 16; o; o >>= 1) ss += __shfl_xor_sync(0xffffffffu, ss, o);
    if ((threadIdx.x & 31) == 0) red[threadIdx.x >> 5] = ss;
    __syncthreads();
    float r = rsqrtf((red[0] + red[1] + red[2] + red[3]) * (1.f / DM) + 1e-5f);
#pragma unroll
    for (int i = 0; i < 3; i++) {
        int c = threadIdx.x + i * 128;
        out[base + c] = v[i] * r * nf[c];
    }
}

// ---------------- generic tiled GEMM -------------------------------------------
// BMxBN tile, 256 threads, TMxTN per thread, BK=16, double-buffered.
// A: [M,K] row-major (k contiguous). B: TB=1 -> [N,K]; TB=0 -> [K,N].
// EPI 0: C[m*ldc+n]
// EPI 1: transposed C[n*ldc+m] + patch-embed adds (e0 bias[m], e1 pos, e2 temp)
// EPI 2: C[m*ldc+n] = softplus(v + e0[m])
// EPI 3: transposed C[n*ldc+m]
template<int BM, int BN, int TM, int TN, int TB, int EPI>
__global__ void __launch_bounds__(256, 2)
k_gemm(const float* __restrict__ A, const float* __restrict__ B,
       float* __restrict__ C, int M, int N, int K,
       int lda, int ldb, int ldc, long zA, long zB, long zC,
       const float* __restrict__ e0, const float* __restrict__ e1,
       const float* __restrict__ e2)
{
    constexpr int AF = (BM * 16) / 1024;   // float4 per thread for A stage
    constexpr int BF = (BN * 16) / 1024;
    __shared__ float As[2][16][BM + 4];
    __shared__ float Bs[2][16][BN + 4];
    A += blockIdx.z * zA; B += blockIdx.z * zB; C += blockIdx.z * zC;
    const int m0 = blockIdx.y * BM, n0 = blockIdx.x * BN;
    const int tid = threadIdx.x;
    const int tx = tid % (BN / TN), ty = tid / (BN / TN);
    float4 pa[AF], pb[BF];

    auto fetch = [&](int k0) {
#pragma unroll
        for (int i = 0; i < AF; i++) {
            int idx = tid + i * 256;
            int row = idx >> 2, k = k0 + (idx & 3) * 4;
            int m = m0 + row;
            pa[i] = (m < M && k < K) ? *(const float4*)(A + (long)m * lda + k)
                                     : make_float4(0.f, 0.f, 0.f, 0.f);
        }
#pragma unroll
        for (int i = 0; i < BF; i++) {
            int idx = tid + i * 256;
            if (TB) {
                int row = idx >> 2, k = k0 + (idx & 3) * 4;
                int n = n0 + row;
                pb[i] = (n < N && k < K) ? *(const float4*)(B + (long)n * ldb + k)
                                         : make_float4(0.f, 0.f, 0.f, 0.f);
            } else {
                int k = idx / (BN / 4), n = n0 + (idx % (BN / 4)) * 4;
                pb[i] = (k0 + k < K && n < N)
                      ? *(const float4*)(B + (long)(k0 + k) * ldb + n)
                      : make_float4(0.f, 0.f, 0.f, 0.f);
            }
        }
    };
    auto stage = [&](int s) {
#pragma unroll
        for (int i = 0; i < AF; i++) {
            int idx = tid + i * 256;
            int row = idx >> 2, c = (idx & 3) * 4;
            As[s][c + 0][row] = pa[i].x; As[s][c + 1][row] = pa[i].y;
            As[s][c + 2][row] = pa[i].z; As[s][c + 3][row] = pa[i].w;
        }
#pragma unroll
        for (int i = 0; i < BF; i++) {
            int idx = tid + i * 256;
            if (TB) {
                int row = idx >> 2, c = (idx & 3) * 4;
                Bs[s][c + 0][row] = pb[i].x; Bs[s][c + 1][row] = pb[i].y;
                Bs[s][c + 2][row] = pb[i].z; Bs[s][c + 3][row] = pb[i].w;
            } else {
                int k = idx / (BN / 4), n4 = (idx % (BN / 4)) * 4;
                *(float4*)&Bs[s][k][n4] = pb[i];
            }
        }
    };

    float acc[TM][TN];
#pragma unroll
    for (int i = 0; i < TM; i++)
#pragma unroll
        for (int j = 0; j < TN; j++) acc[i][j] = 0.f;

    const int nt = (K + 15) >> 4;
    fetch(0); stage(0); __syncthreads();
    for (int t = 0; t < nt; t++) {
        int cur = t & 1;
        if (t + 1 < nt) fetch((t + 1) << 4);
#pragma unroll
        for (int k = 0; k < 16; k++) {
            float a[TM], b[TN];
#pragma unroll
            for (int i = 0; i < TM / 4; i++)
                *(float4*)&a[4 * i] = *(const float4*)&As[cur][k][ty * TM + 4 * i];
#pragma unroll
            for (int j = 0; j < TN / 4; j++)
                *(float4*)&b[4 * j] = *(const float4*)&Bs[cur][k][tx * TN + 4 * j];
#pragma unroll
            for (int i = 0; i < TM; i++)
#pragma unroll
                for (int j = 0; j < TN; j++)
                    acc[i][j] = fmaf(a[i], b[j], acc[i][j]);
        }
        if (t + 1 < nt) stage(cur ^ 1);
        __syncthreads();
    }

    if (EPI == 0 || EPI == 2) {
#pragma unroll
        for (int i = 0; i < TM; i++) {
            int m = m0 + ty * TM + i;
            if (m >= M) continue;
            float bb = (EPI == 2) ? e0[m] : 0.f;
#pragma unroll
            for (int j4 = 0; j4 < TN / 4; j4++) {
                int n = n0 + tx * TN + j4 * 4;
                if (n >= N) continue;
                float4 v = *(float4*)&acc[i][j4 * 4];
                if (EPI == 2) {
                    v.x += bb; v.y += bb; v.z += bb; v.w += bb;
                    v.x = (v.x > 20.f) ? v.x : log1pf(__expf(v.x));
                    v.y = (v.y > 20.f) ? v.y : log1pf(__expf(v.y));
                    v.z = (v.z > 20.f) ? v.z : log1pf(__expf(v.z));
                    v.w = (v.w > 20.f) ? v.w : log1pf(__expf(v.w));
                }
                *(float4*)(C + (long)m * ldc + n) = v;
            }
        }
    } else {
#pragma unroll
        for (int j = 0; j < TN; j++) {
            int n = n0 + tx * TN + j;
            if (n >= N) continue;
            float vv[TM];
#pragma unroll
            for (int i = 0; i < TM; i++) {
                float v = acc[i][j];
                if (EPI == 1) {
                    int m = m0 + ty * TM + i;
                    v += e0[m] + e1[(n % 196) * DM + m] + e2[((n / 196) & 7) * DM + m];
                }
                vv[i] = v;
            }
#pragma unroll
            for (int i = 0; i < TM / 4; i++)
                *(float4*)(C + (long)n * ldc + m0 + ty * TM + 4 * i) = *(float4*)&vv[4 * i];
        }
    }
}

// causal depthwise conv (K=4) + silu; sums the two in_proj split-K partials.
__global__ void k_conv(const float* __restrict__ cwf, const float* __restrict__ cbf,
                       const float* __restrict__ cwb, const float* __restrict__ cbb) {
    int idx = blockIdx.x * blockDim.x + threadIdx.x;
    if (idx >= DI * LTOT) return;
    int dir = blockIdx.y;
    int d = idx / LTOT, bl = idx % LTOT;
    int b = bl / LSEQ, p = bl % LSEQ;
    const float* w = (dir ? cwb : cwf) + d * 4;
    float acc = (dir ? cbb : cbf)[d];
    long off = (long)d * LTOT + b * LSEQ;
    const float* x0 = g_xzp + off;
    const float* x1 = g_xzp + 2L * DI * LTOT + off;
#pragma unroll
    for (int k = 0; k < 4; k++) {
        int q = p - 3 + k;
        if (q >= 0) {
            int l = dir ? (LSEQ - 1 - q) : q;
            acc += w[k] * (x0[l] + x1[l]);
        }
    }
    g_xc[((long)dir * DI + d) * LTOT + bl] = acc / (1.f + __expf(-acc));
}

// reduce xproj split-K partials and route: rows 0..23 -> xdt24, 24..39 -> btr, 40..55 -> ctr
__global__ void k_xpred_bct() {
    int idx = blockIdx.x * blockDim.x + threadIdx.x;
    if (idx >= 2 * 56 * LTOT) return;
    int dir = idx / (56 * LTOT);
    int rem = idx % (56 * LTOT);
    int r = rem / LTOT, bl = rem % LTOT;
    long base = (long)dir * 4 * 56 * LTOT + rem;
    float s = g_xpart[base] + g_xpart[base + 56L * LTOT]
            + g_xpart[base + 112L * LTOT] + g_xpart[base + 168L * LTOT];
    if (r < 24) {
        g_xdt24[((long)dir * 24 + r) * LTOT + bl] = s;
    } else {
        int b = bl / LSEQ, p = bl % LSEQ;
        long o = (((long)dir * BATCHSZ + b) * LSEQ + p) * DST + ((r - 24) & 15);
        if (r < 40) g_btr[o] = s; else g_ctr[o] = s;
    }
}

// selective scan: one thread per (dir,b,d,n); writes y' = ys + Dp*xc, bwd flipped.
__global__ void k_scan(const float* __restrict__ Alog_f, const float* __restrict__ Alog_b,
                       const float* __restrict__ Dpf, const float* __restrict__ Dpb) {
    int gid = blockIdx.x * (blockDim.x >> 4) + (threadIdx.x >> 4);
    if (gid >= 2 * BATCHSZ * DI) return;
    int n = threadIdx.x & 15;
    int dir = gid / (BATCHSZ * DI);
    int r = gid % (BATCHSZ * DI);
    int b = r / DI, d = r % DI;
    float acoef = -__expf((dir ? Alog_b : Alog_f)[d * DST + n]);
    float dcoef = (dir ? Dpb : Dpf)[d];
    long chan = ((long)dir * DI + d) * LTOT + b * LSEQ;
    const float* dtp = g_dt + chan;
    const float* xcp = g_xc + chan;
    float* ysp = g_ys + chan;
    long bc0 = ((long)dir * BATCHSZ + b) * LSEQ * (long)DST;
    const float* btp = g_btr + bc0;
    const float* ctp = g_ctr + bc0;
    float h = 0.f;
    for (int p0 = 0; p0 < LSEQ; p0 += 4) {
        float4 dt4 = *(const float4*)(dtp + p0);
        float4 xc4 = *(const float4*)(xcp + p0);
        float dts[4] = {dt4.x, dt4.y, dt4.z, dt4.w};
        float xcs[4] = {xc4.x, xc4.y, xc4.z, xc4.w};
#pragma unroll
        for (int j = 0; j < 4; j++) {
            int p = p0 + j;
            float a = __expf(dts[j] * acoef);
            float u = dts[j] * xcs[j] * btp[p * DST + n];
            h = fmaf(a, h, u);
            float py = h * ctp[p * DST + n];
            py += __shfl_xor_sync(0xffffffffu, py, 1);
            py += __shfl_xor_sync(0xffffffffu, py, 2);
            py += __shfl_xor_sync(0xffffffffu, py, 4);
            py += __shfl_xor_sync(0xffffffffu, py, 8);
            if (n == 0) {
                int op = dir ? (LSEQ - 1 - p) : p;
                ysp[op] = py + dcoef * xcs[j];
            }
        }
    }
}

// ycomb = (y'_f + y'_b) * silu(z);  z summed from the two in_proj partials
__global__ void k_combine() {
    int i4 = blockIdx.x * blockDim.x + threadIdx.x;
    if (i4 >= DI * LTOT / 4) return;
    long i = (long)i4 * 4;
    float4 z0 = *(const float4*)(g_xzp + (long)DI * LTOT + i);
    float4 z1 = *(const float4*)(g_xzp + 3L * DI * LTOT + i);
    float4 yf = *(const float4*)(g_ys + i);
    float4 yb = *(const float4*)(g_ys + (long)DI * LTOT + i);
    float4 o;
    float z;
    z = z0.x + z1.x; o.x = (yf.x + yb.x) * z / (1.f + __expf(-z));
    z = z0.y + z1.y; o.y = (yf.y + yb.y) * z / (1.f + __expf(-z));
    z = z0.z + z1.z; o.z = (yf.z + yb.z) * z / (1.f + __expf(-z));
    z = z0.w + z1.w; o.w = (yf.w + yb.w) * z / (1.f + __expf(-z));
    *(float4*)(g_ycomb + i) = o;
}

// ---------------- host ----------------
extern "C" void kernel_launch(void* const* d_in, const int* in_sizes, int n_in,
                              void* d_out, int out_size) {
    const float* x        = (const float*)d_in[0];
    const float* patch_w  = (const float*)d_in[1];
    const float* patch_b  = (const float*)d_in[2];
    const float* pos      = (const float*)d_in[3];
    const float* temp     = (const float*)d_in[4];
    const float* in_proj  = (const float*)d_in[5];
    const float* conv_w   = (const float*)d_in[6];
    const float* conv_b   = (const float*)d_in[7];
    const float* xproj_w  = (const float*)d_in[8];
    const float* dt_w     = (const float*)d_in[9];
    const float* dt_b     = (const float*)d_in[10];
    const float* A_log    = (const float*)d_in[11];
    const float* Dp       = (const float*)d_in[12];
    const float* conv_wb  = (const float*)d_in[13];
    const float* conv_bb  = (const float*)d_in[14];
    const float* xproj_wb = (const float*)d_in[15];
    const float* dt_wb    = (const float*)d_in[16];
    const float* dt_bb    = (const float*)d_in[17];
    const float* A_logb   = (const float*)d_in[18];
    const float* Dpb      = (const float*)d_in[19];
    const float* out_proj = (const float*)d_in[20];
    const float* norm_w   = (const float*)d_in[21];
    const float* norm_f   = (const float*)d_in[22];

    float *p_patches, *p_hidden, *p_resid, *p_norm, *p_xzp, *p_xc, *p_dt,
          *p_xpart, *p_xdt24, *p_ycomb;
    cudaGetSymbolAddress((void**)&p_patches, g_patches);
    cudaGetSymbolAddress((void**)&p_hidden,  g_hidden);
    cudaGetSymbolAddress((void**)&p_resid,   g_resid);
    cudaGetSymbolAddress((void**)&p_norm,    g_norm);
    cudaGetSymbolAddress((void**)&p_xzp,     g_xzp);
    cudaGetSymbolAddress((void**)&p_xc,      g_xc);
    cudaGetSymbolAddress((void**)&p_dt,      g_dt);
    cudaGetSymbolAddress((void**)&p_xpart,   g_xpart);
    cudaGetSymbolAddress((void**)&p_xdt24,   g_xdt24);
    cudaGetSymbolAddress((void**)&p_ycomb,   g_ycomb);

    k_patch_gather<<<(NPATCH * PKDIM + 255) / 256, 256>>>(x);
    k_zero<<<(LTOT * DM + 255) / 256, 256>>>(p_resid, LTOT * DM);
    // patch embed (transposed store + pos adds): hidden[bl, m]
    k_gemm<128, 128, 8, 8, 1, 1><<<dim3(25, 3, 1), 256>>>(
        patch_w, p_patches, p_hidden, DM, LTOT, PKDIM,
        PKDIM, PKDIM, DM, 0, 0, 0, patch_b, pos, temp);

    for (int ly = 0; ly < DEPTH; ly++) {
        k_prenorm<<<LTOT, 128>>>(norm_w + ly * DM);

        // in_proj split-K=2: xz_partial[z][e, bl]
        k_gemm<128, 128, 8, 8, 1, 0><<<dim3(25, 12, 2), 256>>>(
            in_proj + (long)ly * 2 * DI * DM, p_norm, p_xzp,
            2 * DI, LTOT, 192, DM, DM, LTOT,
            192, 192, 2L * DI * LTOT, nullptr, nullptr, nullptr);

        {
            dim3 g((DI * LTOT + 255) / 256, 2);
            k_conv<<<g, 256>>>(conv_w + (long)ly * DI * 4, conv_b + (long)ly * DI,
                               conv_wb + (long)ly * DI * 4, conv_bb + (long)ly * DI);
        }

        for (int dir = 0; dir < 2; dir++) {
            const float* xpw = (dir ? xproj_wb : xproj_w) + (long)ly * 56 * DI;
            k_gemm<64, 64, 4, 4, 0, 0><<<dim3(49, 1, 4), 256>>>(
                xpw, p_xc + (long)dir * DI * LTOT, p_xpart + (long)dir * 4 * 56 * LTOT,
                56, LTOT, 192, DI, LTOT, LTOT,
                192, 192L * LTOT, 56L * LTOT, nullptr, nullptr, nullptr);
        }
        k_xpred_bct<<<(2 * 56 * LTOT + 255) / 256, 256>>>();

        for (int dir = 0; dir < 2; dir++) {
            const float* dw = (dir ? dt_wb : dt_w) + (long)ly * DI * DTR;
            const float* db = (dir ? dt_bb : dt_b) + (long)ly * DI;
            k_gemm<128, 128, 8, 8, 0, 2><<<dim3(25, 6, 1), 256>>>(
                dw, p_xdt24 + (long)dir * 24 * LTOT, p_dt + (long)dir * DI * LTOT,
                DI, LTOT, DTR, DTR, LTOT, LTOT, 0, 0, 0,
                db, nullptr, nullptr);
        }

        k_scan<<<192, 256>>>(A_log + (long)ly * DI * DST, A_logb + (long)ly * DI * DST,
                             Dp + (long)ly * DI, Dpb + (long)ly * DI);
        k_combine<<<(DI * LTOT / 4 + 255) / 256, 256>>>();

        // out_proj (transposed store): hidden[bl, o]
        k_gemm<128, 64, 8, 4, 0, 3><<<dim3(49, 3, 1), 256>>>(
            out_proj + (long)ly * DM * DI, p_ycomb, p_hidden,
            DM, LTOT, DI, DI, LTOT, DM, 0, 0, 0,
            nullptr, nullptr, nullptr);
    }

    k_final<<<LTOT, 128>>>(norm_f, (float*)d_out);
}

// round 4
// speedup vs baseline: 1.0072x; 1.0072x over previous
#include <cuda_runtime.h>

#define BATCHSZ 2
#define DM      384
#define DI      768
#define LSEQ    1568
#define LTOT    3136
#define DTR     24
#define DST     16
#define DEPTH   24
#define NPATCH  3136
#define PKDIM   768

// ---------------- scratch ----------------
__device__ float g_patches[NPATCH * PKDIM];
__device__ float g_hidden [LTOT * DM];
__device__ float g_resid  [LTOT * DM];
__device__ float g_norm   [LTOT * DM];
__device__ float g_xz     [2 * DI * LTOT];          // (e, bl)
__device__ float g_xc     [2 * DI * LTOT];          // (dir*DI+d, bl)
__device__ float g_dt     [2 * DI * LTOT];
__device__ float g_xpart  [2 * 4 * 56 * LTOT];      // xproj split-K partials
__device__ float g_xdt24  [2 * 24 * LTOT];
__device__ float g_btr    [2 * BATCHSZ * LSEQ * DST];
__device__ float g_ctr    [2 * BATCHSZ * LSEQ * DST];
__device__ float g_ys     [2 * DI * LTOT];          // y' = ys + Dp*xc, bwd flipped
__device__ float g_ycomb  [DI * LTOT];

__global__ void k_zero(float* p, int n) {
    int i = blockIdx.x * blockDim.x + threadIdx.x;
    if (i < n) p[i] = 0.f;
}

__global__ void k_patch_gather(const float* __restrict__ x) {
    int idx = blockIdx.x * blockDim.x + threadIdx.x;
    if (idx >= NPATCH * PKDIM) return;
    int row = idx / PKDIM, c = idx % PKDIM;
    int b = row / 1568; int rem = row % 1568; int t = rem / 196; int n = rem % 196;
    int gy = n / 14, gx = n % 14;
    int ch = c / 256; int r = c % 256; int py = r / 16, px = r % 16;
    g_patches[idx] = x[(((long)(b * 3 + ch) * 8 + t) * 224 + gy * 16 + py) * 224 + gx * 16 + px];
}

// res += hidden; norm = rmsnorm(res)*nw
__global__ void k_prenorm(const float* __restrict__ nw) {
    int base = blockIdx.x * DM;
    __shared__ float red[4];
    float v[3]; float ss = 0.f;
#pragma unroll
    for (int i = 0; i < 3; i++) {
        int c = threadIdx.x + i * 128;
        float t = g_resid[base + c] + g_hidden[base + c];
        g_resid[base + c] = t; v[i] = t; ss += t * t;
    }
#pragma unroll
    for (int o = 16; o; o >>= 1) ss += __shfl_xor_sync(0xffffffffu, ss, o);
    if ((threadIdx.x & 31) == 0) red[threadIdx.x >> 5] = ss;
    __syncthreads();
    float r = rsqrtf((red[0] + red[1] + red[2] + red[3]) * (1.f / DM) + 1e-5f);
#pragma unroll
    for (int i = 0; i < 3; i++) {
        int c = threadIdx.x + i * 128;
        g_norm[base + c] = v[i] * r * nw[c];
    }
}

__global__ void k_final(const float* __restrict__ nf, float* __restrict__ out) {
    int base = blockIdx.x * DM;
    __shared__ float red[4];
    float v[3]; float ss = 0.f;
#pragma unroll
    for (int i = 0; i < 3; i++) {
        int c = threadIdx.x + i * 128;
        float t = g_resid[base + c] + g_hidden[base + c];
        v[i] = t; ss += t * t;
    }
#pragma unroll
    for (int o = 16; o; o >>= 1) ss += __shfl_xor_sync(0xffffffffu, ss, o);
    if ((threadIdx.x & 31) == 0) red[threadIdx.x >> 5] = ss;
    __syncthreads();
    float r = rsqrtf((red[0] + red[1] + red[2] + red[3]) * (1.f / DM) + 1e-5f);
#pragma unroll
    for (int i = 0; i < 3; i++) {
        int c = threadIdx.x + i * 128;
        out[base + c] = v[i] * r * nf[c];
    }
}

// ---------------- tiled GEMM: BMxBN tile, 256 thr, TMxTN/thread, BK=16, dbl-buffered
// A: [M,K] row-major. B: TB=1 -> [N,K]; TB=0 -> [K,N].
// EPI 0: C[m*ldc+n]
// EPI 1: transposed C[n*ldc+m] + patch adds (e0 bias[m], e1 pos, e2 temp)
// EPI 2: C[m*ldc+n] = softplus(v + e0[m])
// EPI 3: transposed C[n*ldc+m]
template<int BM, int BN, int TM, int TN, int TB, int EPI>
__global__ void __launch_bounds__(256)
k_gemm(const float* __restrict__ A, const float* __restrict__ B,
       float* __restrict__ C, int M, int N, int K,
       int lda, int ldb, int ldc, long zA, long zB, long zC,
       const float* __restrict__ e0, const float* __restrict__ e1,
       const float* __restrict__ e2)
{
    constexpr int AF = (BM * 16) / 1024;
    constexpr int BF = (BN * 16) / 1024;
    __shared__ float As[2][16][BM + 4];
    __shared__ float Bs[2][16][BN + 4];
    A += blockIdx.z * zA; B += blockIdx.z * zB; C += blockIdx.z * zC;
    const int m0 = blockIdx.y * BM, n0 = blockIdx.x * BN;
    const int tid = threadIdx.x;
    const int tx = tid % (BN / TN), ty = tid / (BN / TN);
    float4 pa[AF], pb[BF];

    auto fetch = [&](int k0) {
#pragma unroll
        for (int i = 0; i < AF; i++) {
            int idx = tid + i * 256;
            int row = idx >> 2, k = k0 + (idx & 3) * 4;
            int m = m0 + row;
            pa[i] = (m < M && k < K) ? *(const float4*)(A + (long)m * lda + k)
                                     : make_float4(0.f, 0.f, 0.f, 0.f);
        }
#pragma unroll
        for (int i = 0; i < BF; i++) {
            int idx = tid + i * 256;
            if (TB) {
                int row = idx >> 2, k = k0 + (idx & 3) * 4;
                int n = n0 + row;
                pb[i] = (n < N && k < K) ? *(const float4*)(B + (long)n * ldb + k)
                                         : make_float4(0.f, 0.f, 0.f, 0.f);
            } else {
                int k = idx / (BN / 4), n = n0 + (idx % (BN / 4)) * 4;
                pb[i] = (k0 + k < K && n < N)
                      ? *(const float4*)(B + (long)(k0 + k) * ldb + n)
                      : make_float4(0.f, 0.f, 0.f, 0.f);
            }
        }
    };
    auto stage = [&](int s) {
#pragma unroll
        for (int i = 0; i < AF; i++) {
            int idx = tid + i * 256;
            int row = idx >> 2, c = (idx & 3) * 4;
            As[s][c + 0][row] = pa[i].x; As[s][c + 1][row] = pa[i].y;
            As[s][c + 2][row] = pa[i].z; As[s][c + 3][row] = pa[i].w;
        }
#pragma unroll
        for (int i = 0; i < BF; i++) {
            int idx = tid + i * 256;
            if (TB) {
                int row = idx >> 2, c = (idx & 3) * 4;
                Bs[s][c + 0][row] = pb[i].x; Bs[s][c + 1][row] = pb[i].y;
                Bs[s][c + 2][row] = pb[i].z; Bs[s][c + 3][row] = pb[i].w;
            } else {
                int k = idx / (BN / 4), n4 = (idx % (BN / 4)) * 4;
                *(float4*)&Bs[s][k][n4] = pb[i];
            }
        }
    };

    float acc[TM][TN];
#pragma unroll
    for (int i = 0; i < TM; i++)
#pragma unroll
        for (int j = 0; j < TN; j++) acc[i][j] = 0.f;

    const int nt = (K + 15) >> 4;
    fetch(0); stage(0); __syncthreads();
    for (int t = 0; t < nt; t++) {
        int cur = t & 1;
        if (t + 1 < nt) fetch((t + 1) << 4);
#pragma unroll
        for (int k = 0; k < 16; k++) {
            float a[TM], b[TN];
#pragma unroll
            for (int i = 0; i < TM / 4; i++)
                *(float4*)&a[4 * i] = *(const float4*)&As[cur][k][ty * TM + 4 * i];
#pragma unroll
            for (int j = 0; j < TN / 4; j++)
                *(float4*)&b[4 * j] = *(const float4*)&Bs[cur][k][tx * TN + 4 * j];
#pragma unroll
            for (int i = 0; i < TM; i++)
#pragma unroll
                for (int j = 0; j < TN; j++)
                    acc[i][j] = fmaf(a[i], b[j], acc[i][j]);
        }
        if (t + 1 < nt) stage(cur ^ 1);
        __syncthreads();
    }

    if (EPI == 0 || EPI == 2) {
#pragma unroll
        for (int i = 0; i < TM; i++) {
            int m = m0 + ty * TM + i;
            if (m >= M) continue;
            float bb = (EPI == 2) ? e0[m] : 0.f;
#pragma unroll
            for (int j4 = 0; j4 < TN / 4; j4++) {
                int n = n0 + tx * TN + j4 * 4;
                if (n >= N) continue;
                float4 v = *(float4*)&acc[i][j4 * 4];
                if (EPI == 2) {
                    v.x += bb; v.y += bb; v.z += bb; v.w += bb;
                    v.x = (v.x > 20.f) ? v.x : log1pf(__expf(v.x));
                    v.y = (v.y > 20.f) ? v.y : log1pf(__expf(v.y));
                    v.z = (v.z > 20.f) ? v.z : log1pf(__expf(v.z));
                    v.w = (v.w > 20.f) ? v.w : log1pf(__expf(v.w));
                }
                *(float4*)(C + (long)m * ldc + n) = v;
            }
        }
    } else {
#pragma unroll
        for (int j = 0; j < TN; j++) {
            int n = n0 + tx * TN + j;
            if (n >= N) continue;
            float vv[TM];
#pragma unroll
            for (int i = 0; i < TM; i++) {
                float v = acc[i][j];
                if (EPI == 1) {
                    int m = m0 + ty * TM + i;
                    v += e0[m] + e1[(n % 196) * DM + m] + e2[((n / 196) & 7) * DM + m];
                }
                vv[i] = v;
            }
#pragma unroll
            for (int i = 0; i < TM / 4; i++)
                *(float4*)(C + (long)n * ldc + m0 + ty * TM + 4 * i) = *(float4*)&vv[4 * i];
        }
    }
}

// causal depthwise conv (K=4) + silu
__global__ void k_conv(const float* __restrict__ cwf, const float* __restrict__ cbf,
                       const float* __restrict__ cwb, const float* __restrict__ cbb) {
    int idx = blockIdx.x * blockDim.x + threadIdx.x;
    if (idx >= DI * LTOT) return;
    int dir = blockIdx.y;
    int d = idx / LTOT, bl = idx % LTOT;
    int b = bl / LSEQ, p = bl % LSEQ;
    const float* w = (dir ? cwb : cwf) + d * 4;
    float acc = (dir ? cbb : cbf)[d];
    const float* xi = g_xz + (long)d * LTOT + b * LSEQ;
#pragma unroll
    for (int k = 0; k < 4; k++) {
        int q = p - 3 + k;
        if (q >= 0) acc += w[k] * xi[dir ? (LSEQ - 1 - q) : q];
    }
    g_xc[((long)dir * DI + d) * LTOT + bl] = acc / (1.f + __expf(-acc));
}

// reduce xproj split-K partials; route rows 0..23 -> xdt24, 24..39 -> btr, 40..55 -> ctr
__global__ void k_xpred_bct() {
    int idx = blockIdx.x * blockDim.x + threadIdx.x;
    if (idx >= 2 * 56 * LTOT) return;
    int dir = idx / (56 * LTOT);
    int rem = idx % (56 * LTOT);
    int r = rem / LTOT, bl = rem % LTOT;
    long base = (long)dir * 4 * 56 * LTOT + rem;
    float s = g_xpart[base] + g_xpart[base + 56L * LTOT]
            + g_xpart[base + 112L * LTOT] + g_xpart[base + 168L * LTOT];
    if (r < 24) {
        g_xdt24[((long)dir * 24 + r) * LTOT + bl] = s;
    } else {
        int b = bl / LSEQ, p = bl % LSEQ;
        long o = (((long)dir * BATCHSZ + b) * LSEQ + p) * DST + ((r - 24) & 15);
        if (r < 40) g_btr[o] = s; else g_ctr[o] = s;
    }
}

// selective scan: one thread per (dir,b,d,n); writes y' = ys + Dp*xc, bwd flipped.
__global__ void k_scan(const float* __restrict__ Alog_f, const float* __restrict__ Alog_b,
                       const float* __restrict__ Dpf, const float* __restrict__ Dpb) {
    int gid = blockIdx.x * (blockDim.x >> 4) + (threadIdx.x >> 4);
    if (gid >= 2 * BATCHSZ * DI) return;
    int n = threadIdx.x & 15;
    int dir = gid / (BATCHSZ * DI);
    int r = gid % (BATCHSZ * DI);
    int b = r / DI, d = r % DI;
    float acoef = -__expf((dir ? Alog_b : Alog_f)[d * DST + n]);
    float dcoef = (dir ? Dpb : Dpf)[d];
    long chan = ((long)dir * DI + d) * LTOT + b * LSEQ;
    const float* dtp = g_dt + chan;
    const float* xcp = g_xc + chan;
    float* ysp = g_ys + chan;
    long bc0 = ((long)dir * BATCHSZ + b) * LSEQ * (long)DST;
    const float* btp = g_btr + bc0;
    const float* ctp = g_ctr + bc0;
    float h = 0.f;
    for (int p0 = 0; p0 < LSEQ; p0 += 4) {
        float4 dt4 = *(const float4*)(dtp + p0);
        float4 xc4 = *(const float4*)(xcp + p0);
        float dts[4] = {dt4.x, dt4.y, dt4.z, dt4.w};
        float xcs[4] = {xc4.x, xc4.y, xc4.z, xc4.w};
#pragma unroll
        for (int j = 0; j < 4; j++) {
            int p = p0 + j;
            float a = __expf(dts[j] * acoef);
            float u = dts[j] * xcs[j] * btp[p * DST + n];
            h = fmaf(a, h, u);
            float py = h * ctp[p * DST + n];
            py += __shfl_xor_sync(0xffffffffu, py, 1);
            py += __shfl_xor_sync(0xffffffffu, py, 2);
            py += __shfl_xor_sync(0xffffffffu, py, 4);
            py += __shfl_xor_sync(0xffffffffu, py, 8);
            if (n == 0) {
                int op = dir ? (LSEQ - 1 - p) : p;
                ysp[op] = py + dcoef * xcs[j];
            }
        }
    }
}

// ycomb = (y'_f + y'_b) * silu(z)
__global__ void k_combine() {
    int i4 = blockIdx.x * blockDim.x + threadIdx.x;
    if (i4 >= DI * LTOT / 4) return;
    long i = (long)i4 * 4;
    float4 zz = *(const float4*)(g_xz + (long)DI * LTOT + i);
    float4 yf = *(const float4*)(g_ys + i);
    float4 yb = *(const float4*)(g_ys + (long)DI * LTOT + i);
    float4 o;
    o.x = (yf.x + yb.x) * zz.x / (1.f + __expf(-zz.x));
    o.y = (yf.y + yb.y) * zz.y / (1.f + __expf(-zz.y));
    o.z = (yf.z + yb.z) * zz.z / (1.f + __expf(-zz.z));
    o.w = (yf.w + yb.w) * zz.w / (1.f + __expf(-zz.w));
    *(float4*)(g_ycomb + i) = o;
}

// ---------------- host ----------------
extern "C" void kernel_launch(void* const* d_in, const int* in_sizes, int n_in,
                              void* d_out, int out_size) {
    const float* x        = (const float*)d_in[0];
    const float* patch_w  = (const float*)d_in[1];
    const float* patch_b  = (const float*)d_in[2];
    const float* pos      = (const float*)d_in[3];
    const float* temp     = (const float*)d_in[4];
    const float* in_proj  = (const float*)d_in[5];
    const float* conv_w   = (const float*)d_in[6];
    const float* conv_b   = (const float*)d_in[7];
    const float* xproj_w  = (const float*)d_in[8];
    const float* dt_w     = (const float*)d_in[9];
    const float* dt_b     = (const float*)d_in[10];
    const float* A_log    = (const float*)d_in[11];
    const float* Dp       = (const float*)d_in[12];
    const float* conv_wb  = (const float*)d_in[13];
    const float* conv_bb  = (const float*)d_in[14];
    const float* xproj_wb = (const float*)d_in[15];
    const float* dt_wb    = (const float*)d_in[16];
    const float* dt_bb    = (const float*)d_in[17];
    const float* A_logb   = (const float*)d_in[18];
    const float* Dpb      = (const float*)d_in[19];
    const float* out_proj = (const float*)d_in[20];
    const float* norm_w   = (const float*)d_in[21];
    const float* norm_f   = (const float*)d_in[22];

    float *p_patches, *p_hidden, *p_resid, *p_norm, *p_xz, *p_xc, *p_dt,
          *p_xpart, *p_xdt24, *p_ycomb;
    cudaGetSymbolAddress((void**)&p_patches, g_patches);
    cudaGetSymbolAddress((void**)&p_hidden,  g_hidden);
    cudaGetSymbolAddress((void**)&p_resid,   g_resid);
    cudaGetSymbolAddress((void**)&p_norm,    g_norm);
    cudaGetSymbolAddress((void**)&p_xz,      g_xz);
    cudaGetSymbolAddress((void**)&p_xc,      g_xc);
    cudaGetSymbolAddress((void**)&p_dt,      g_dt);
    cudaGetSymbolAddress((void**)&p_xpart,   g_xpart);
    cudaGetSymbolAddress((void**)&p_xdt24,   g_xdt24);
    cudaGetSymbolAddress((void**)&p_ycomb,   g_ycomb);

    k_patch_gather<<<(NPATCH * PKDIM + 255) / 256, 256>>>(x);
    k_zero<<<(LTOT * DM + 255) / 256, 256>>>(p_resid, LTOT * DM);
    // patch embed (transposed store + pos adds): hidden[bl, m]
    k_gemm<128, 64, 8, 4, 1, 1><<<dim3(49, 3, 1), 256>>>(
        patch_w, p_patches, p_hidden, DM, LTOT, PKDIM,
        PKDIM, PKDIM, DM, 0, 0, 0, patch_b, pos, temp);

    for (int ly = 0; ly < DEPTH; ly++) {
        k_prenorm<<<LTOT, 128>>>(norm_w + ly * DM);

        // in_proj: xz[e, bl] = W[e,:] . norm[bl,:]
        k_gemm<128, 64, 8, 4, 1, 0><<<dim3(49, 12, 1), 256>>>(
            in_proj + (long)ly * 2 * DI * DM, p_norm, p_xz,
            2 * DI, LTOT, DM, DM, DM, LTOT, 0, 0, 0,
            nullptr, nullptr, nullptr);

        {
            dim3 g((DI * LTOT + 255) / 256, 2);
            k_conv<<<g, 256>>>(conv_w + (long)ly * DI * 4, conv_b + (long)ly * DI,
                               conv_wb + (long)ly * DI * 4, conv_bb + (long)ly * DI);
        }

        for (int dir = 0; dir < 2; dir++) {
            const float* xpw = (dir ? xproj_wb : xproj_w) + (long)ly * 56 * DI;
            k_gemm<64, 64, 4, 4, 0, 0><<<dim3(49, 1, 4), 256>>>(
                xpw, p_xc + (long)dir * DI * LTOT, p_xpart + (long)dir * 4 * 56 * LTOT,
                56, LTOT, 192, DI, LTOT, LTOT,
                192, 192L * LTOT, 56L * LTOT, nullptr, nullptr, nullptr);
        }
        k_xpred_bct<<<(2 * 56 * LTOT + 255) / 256, 256>>>();

        for (int dir = 0; dir < 2; dir++) {
            const float* dw = (dir ? dt_wb : dt_w) + (long)ly * DI * DTR;
            const float* db = (dir ? dt_bb : dt_b) + (long)ly * DI;
            k_gemm<128, 64, 8, 4, 0, 2><<<dim3(49, 6, 1), 256>>>(
                dw, p_xdt24 + (long)dir * 24 * LTOT, p_dt + (long)dir * DI * LTOT,
                DI, LTOT, DTR, DTR, LTOT, LTOT, 0, 0, 0,
                db, nullptr, nullptr);
        }

        k_scan<<<192, 256>>>(A_log + (long)ly * DI * DST, A_logb + (long)ly * DI * DST,
                             Dp + (long)ly * DI, Dpb + (long)ly * DI);
        k_combine<<<(DI * LTOT / 4 + 255) / 256, 256>>>();

        // out_proj (transposed store): hidden[bl, o]
        k_gemm<128, 64, 8, 4, 0, 3><<<dim3(49, 3, 1), 256>>>(
            out_proj + (long)ly * DM * DI, p_ycomb, p_hidden,
            DM, LTOT, DI, DI, LTOT, DM, 0, 0, 0,
            nullptr, nullptr, nullptr);
    }

    k_final<<<LTOT, 128>>>(norm_f, (float*)d_out);
}

// round 5
// speedup vs baseline: 1.5570x; 1.5458x over previous
#include <cuda_runtime.h>

#define BATCHSZ 2
#define DM      384
#define DI      768
#define LSEQ    1568
#define LTOT    3136      // BATCH * LSEQ
#define DTR     24
#define DST     16
#define DEPTH   24
#define NPATCH  3136
#define PKDIM   768

// ---------------- scratch ----------------
__device__ float g_patches[NPATCH * PKDIM];
__device__ float g_hidden [LTOT * DM];
__device__ float g_resid  [LTOT * DM];
__device__ float g_norm   [LTOT * DM];
__device__ float g_xz     [2 * DI * LTOT];          // (e, bl)
__device__ float g_xc     [2 * DI * LTOT];          // (dir*DI+d, bl)
__device__ float g_dt     [2 * DI * LTOT];
__device__ float g_xpart  [2 * 4 * 56 * LTOT];      // split-K partials
__device__ float g_xdbl   [2 * 56 * LTOT];
__device__ float g_btr    [2 * BATCHSZ * LSEQ * DST];
__device__ float g_ctr    [2 * BATCHSZ * LSEQ * DST];
__device__ float g_ys     [2 * DI * LTOT];
__device__ float g_ycomb  [DI * LTOT];

__global__ void k_zero(float* p, int n) {
    int i = blockIdx.x * blockDim.x + threadIdx.x;
    if (i < n) p[i] = 0.f;
}

__global__ void k_patch_gather(const float* __restrict__ x) {
    int idx = blockIdx.x * blockDim.x + threadIdx.x;
    if (idx >= NPATCH * PKDIM) return;
    int row = idx / PKDIM, c = idx % PKDIM;
    int b = row / 1568; int rem = row % 1568; int t = rem / 196; int n = rem % 196;
    int gy = n / 14, gx = n % 14;
    int ch = c / 256; int r = c % 256; int py = r / 16, px = r % 16;
    g_patches[idx] = x[(((long)(b * 3 + ch) * 8 + t) * 224 + gy * 16 + py) * 224 + gx * 16 + px];
}

// res += hidden; norm = rmsnorm(res)*nw
__global__ void k_prenorm(const float* __restrict__ nw) {
    int base = blockIdx.x * DM;
    __shared__ float red[4];
    float v[3]; float ss = 0.f;
#pragma unroll
    for (int i = 0; i < 3; i++) {
        int c = threadIdx.x + i * 128;
        float t = g_resid[base + c] + g_hidden[base + c];
        g_resid[base + c] = t; v[i] = t; ss += t * t;
    }
#pragma unroll
    for (int o = 16; o; o >>= 1) ss += __shfl_xor_sync(0xffffffffu, ss, o);
    if ((threadIdx.x & 31) == 0) red[threadIdx.x >> 5] = ss;
    __syncthreads();
    float r = rsqrtf((red[0] + red[1] + red[2] + red[3]) * (1.f / DM) + 1e-5f);
#pragma unroll
    for (int i = 0; i < 3; i++) {
        int c = threadIdx.x + i * 128;
        g_norm[base + c] = v[i] * r * nw[c];
    }
}

__global__ void k_final(const float* __restrict__ nf, float* __restrict__ out) {
    int base = blockIdx.x * DM;
    __shared__ float red[4];
    float v[3]; float ss = 0.f;
#pragma unroll
    for (int i = 0; i < 3; i++) {
        int c = threadIdx.x + i * 128;
        float t = g_resid[base + c] + g_hidden[base + c];
        v[i] = t; ss += t * t;
    }
#pragma unroll
    for (int o = 16; o; o >>= 1) ss += __shfl_xor_sync(0xffffffffu, ss, o);
    if ((threadIdx.x & 31) == 0) red[threadIdx.x >> 5] = ss;
    __syncthreads();
    float r = rsqrtf((red[0] + red[1] + red[2] + red[3]) * (1.f / DM) + 1e-5f);
#pragma unroll
    for (int i = 0; i < 3; i++) {
        int c = threadIdx.x + i * 128;
        out[base + c] = v[i] * r * nf[c];
    }
}

// ---------------- GEMM: BMx64x16 tile, 256 thr, TMx4 per thread, double-buffered ----
// A: [M,K] row-major (k contiguous). B: TB=1 -> [N,K]; TB=0 -> [K,N].
// EPI 0: C[m*ldc+n]
// EPI 1: transposed C[n*ldc+m], + patch-embed adds (e0 bias, e1 pos, e2 temp)
// EPI 2: C[m*ldc+n] = softplus(v + e0[m])
// EPI 3: transposed C[n*ldc+m]
template<int BM, int TB, int EPI>
__global__ void __launch_bounds__(256)
k_gemm(const float* __restrict__ A, const float* __restrict__ B,
       float* __restrict__ C, int M, int N, int K,
       int lda, int ldb, int ldc,
       long zA, long zB, long zC,
       const float* __restrict__ e0, const float* __restrict__ e1,
       const float* __restrict__ e2)
{
    constexpr int TM = BM / 16;
    constexpr int AV = BM / 64;
    __shared__ float As[2][16][BM + 4];
    __shared__ float Bs[2][16][68];
    A += blockIdx.z * zA; B += blockIdx.z * zB; C += blockIdx.z * zC;
    const int m0 = blockIdx.y * BM, n0 = blockIdx.x * 64;
    const int tid = threadIdx.x, tx = tid & 15, ty = tid >> 4;
    const int arow = tid >> 2, akc = (tid & 3) * 4;   // A-pattern (also TB=1 B)
    const int bkr = tid >> 4, bnc = (tid & 15) * 4;   // TB=0 B-pattern

    float4 pa[AV], pb;

    auto fetch = [&](int k0) {
#pragma unroll
        for (int i = 0; i < AV; i++) {
            int row = arow + i * 64;
            int m = m0 + row, k = k0 + akc;
            pa[i] = (m < M && k < K) ? *(const float4*)(A + (long)m * lda + k)
                                     : make_float4(0.f, 0.f, 0.f, 0.f);
        }
        if (TB) {
            int n = n0 + arow, k = k0 + akc;
            pb = (k < K) ? *(const float4*)(B + (long)n * ldb + k)
                         : make_float4(0.f, 0.f, 0.f, 0.f);
        } else {
            int k = k0 + bkr;
            pb = (k < K) ? *(const float4*)(B + (long)k * ldb + n0 + bnc)
                         : make_float4(0.f, 0.f, 0.f, 0.f);
        }
    };
    auto stage = [&](int s) {
#pragma unroll
        for (int i = 0; i < AV; i++) {
            int row = arow + i * 64;
            As[s][akc + 0][row] = pa[i].x; As[s][akc + 1][row] = pa[i].y;
            As[s][akc + 2][row] = pa[i].z; As[s][akc + 3][row] = pa[i].w;
        }
        if (TB) {
            Bs[s][akc + 0][arow] = pb.x; Bs[s][akc + 1][arow] = pb.y;
            Bs[s][akc + 2][arow] = pb.z; Bs[s][akc + 3][arow] = pb.w;
        } else {
            *(float4*)&Bs[s][bkr][bnc] = pb;
        }
    };

    float acc[TM][4];
#pragma unroll
    for (int i = 0; i < TM; i++)
#pragma unroll
        for (int j = 0; j < 4; j++) acc[i][j] = 0.f;

    const int nt = (K + 15) >> 4;
    fetch(0); stage(0); __syncthreads();
    for (int t = 0; t < nt; t++) {
        int cur = t & 1;
        if (t + 1 < nt) fetch((t + 1) << 4);
#pragma unroll
        for (int k = 0; k < 16; k++) {
            float a[TM], b[4];
#pragma unroll
            for (int i = 0; i < TM / 4; i++)
                *(float4*)&a[4 * i] = *(const float4*)&As[cur][k][ty * TM + 4 * i];
            *(float4*)&b[0] = *(const float4*)&Bs[cur][k][tx * 4];
#pragma unroll
            for (int i = 0; i < TM; i++)
#pragma unroll
                for (int j = 0; j < 4; j++)
                    acc[i][j] = fmaf(a[i], b[j], acc[i][j]);
        }
        if (t + 1 < nt) stage(cur ^ 1);
        __syncthreads();
    }

    if (EPI == 0 || EPI == 2) {
#pragma unroll
        for (int i = 0; i < TM; i++) {
            int m = m0 + ty * TM + i;
            if (m >= M) continue;
            float4 v = *(float4*)&acc[i][0];
            if (EPI == 2) {
                float bb = e0[m];
                v.x += bb; v.y += bb; v.z += bb; v.w += bb;
                v.x = (v.x > 20.f) ? v.x : log1pf(__expf(v.x));
                v.y = (v.y > 20.f) ? v.y : log1pf(__expf(v.y));
                v.z = (v.z > 20.f) ? v.z : log1pf(__expf(v.z));
                v.w = (v.w > 20.f) ? v.w : log1pf(__expf(v.w));
            }
            *(float4*)(C + (long)m * ldc + n0 + tx * 4) = v;
        }
    } else {
#pragma unroll
        for (int j = 0; j < 4; j++) {
            int n = n0 + tx * 4 + j;
            float vv[TM];
#pragma unroll
            for (int i = 0; i < TM; i++) {
                float v = acc[i][j];
                if (EPI == 1) {
                    int m = m0 + ty * TM + i;
                    v += e0[m] + e1[(n % 196) * DM + m] + e2[((n / 196) & 7) * DM + m];
                }
                vv[i] = v;
            }
#pragma unroll
            for (int i = 0; i < TM / 4; i++)
                *(float4*)(C + (long)n * ldc + m0 + ty * TM + 4 * i) = *(float4*)&vv[4 * i];
        }
    }
}

// reduce split-K partials: xdbl[dir][r][n] = sum_ks xpart[dir][ks][r][n]
__global__ void k_xpred() {
    int idx = blockIdx.x * blockDim.x + threadIdx.x;
    if (idx >= 2 * 56 * LTOT) return;
    int dir = idx / (56 * LTOT);
    int r = idx % (56 * LTOT);
    long base = (long)dir * 4 * 56 * LTOT + r;
    g_xdbl[idx] = g_xpart[base] + g_xpart[base + 56 * LTOT]
                + g_xpart[base + 2L * 56 * LTOT] + g_xpart[base + 3L * 56 * LTOT];
}

// causal depthwise conv (K=4) + silu; bwd reads flipped
__global__ void k_conv(const float* __restrict__ cwf, const float* __restrict__ cbf,
                       const float* __restrict__ cwb, const float* __restrict__ cbb) {
    int idx = blockIdx.x * blockDim.x + threadIdx.x;
    if (idx >= DI * LTOT) return;
    int dir = blockIdx.y;
    int d = idx / LTOT, bl = idx % LTOT;
    int b = bl / LSEQ, p = bl % LSEQ;
    const float* w = (dir ? cwb : cwf) + d * 4;
    float acc = (dir ? cbb : cbf)[d];
    const float* xi = g_xz + (long)d * LTOT + b * LSEQ;
#pragma unroll
    for (int k = 0; k < 4; k++) {
        int q = p - 3 + k;
        if (q >= 0) acc += w[k] * xi[dir ? (LSEQ - 1 - q) : q];
    }
    g_xc[((long)dir * DI + d) * LTOT + bl] = acc / (1.f + __expf(-acc));
}

// transpose B/C rows of xdbl into (dir,b,p,n)
__global__ void k_bc_t() {
    int idx = blockIdx.x * blockDim.x + threadIdx.x;
    if (idx >= 2 * BATCHSZ * LSEQ * DST) return;
    int n = idx & 15;
    int p = (idx >> 4) % LSEQ;
    int db = idx / (16 * LSEQ);
    int dir = db >> 1, b = db & 1;
    long src = (long)dir * 56 * LTOT + b * LSEQ + p;
    g_btr[idx] = g_xdbl[src + (long)(24 + n) * LTOT];
    g_ctr[idx] = g_xdbl[src + (long)(40 + n) * LTOT];
}

// selective scan: one thread per (dir,b,d,n); 16-lane groups reduce over n
__global__ void k_scan(const float* __restrict__ Alog_f, const float* __restrict__ Alog_b) {
    int gid = blockIdx.x * (blockDim.x >> 4) + (threadIdx.x >> 4);
    if (gid >= 2 * BATCHSZ * DI) return;
    int n = threadIdx.x & 15;
    int dir = gid / (BATCHSZ * DI);
    int r = gid % (BATCHSZ * DI);
    int b = r / DI, d = r % DI;
    float acoef = -__expf((dir ? Alog_b : Alog_f)[d * DST + n]);
    long chan = ((long)dir * DI + d) * LTOT + b * LSEQ;
    const float* dtp = g_dt + chan;
    const float* xcp = g_xc + chan;
    float* ysp = g_ys + chan;
    long bc0 = ((long)dir * BATCHSZ + b) * LSEQ * (long)DST;
    const float* btp = g_btr + bc0;
    const float* ctp = g_ctr + bc0;
    float h = 0.f;
#pragma unroll 4
    for (int p = 0; p < LSEQ; p++) {
        float dtv = dtp[p], xcv = xcp[p];
        float a = __expf(dtv * acoef);
        float u = dtv * xcv * btp[p * DST + n];
        h = fmaf(a, h, u);
        float py = h * ctp[p * DST + n];
        py += __shfl_xor_sync(0xffffffffu, py, 1);
        py += __shfl_xor_sync(0xffffffffu, py, 2);
        py += __shfl_xor_sync(0xffffffffu, py, 4);
        py += __shfl_xor_sync(0xffffffffu, py, 8);
        if (n == 0) ysp[p] = py;
    }
}

__global__ void k_combine(const float* __restrict__ Dpf, const float* __restrict__ Dpb) {
    int idx = blockIdx.x * blockDim.x + threadIdx.x;
    if (idx >= DI * LTOT) return;
    int d = idx / LTOT, bl = idx % LTOT;
    int b = bl / LSEQ, l = bl % LSEQ;
    float z = g_xz[((long)DI + d) * LTOT + bl];
    float sg = z / (1.f + __expf(-z));
    long f = (long)d * LTOT + b * LSEQ;
    long bw = ((long)DI + d) * LTOT + b * LSEQ;
    int pb = LSEQ - 1 - l;
    float yf = g_ys[f + l] + Dpf[d] * g_xc[f + l];
    float yb = g_ys[bw + pb] + Dpb[d] * g_xc[bw + pb];
    g_ycomb[f + l] = (yf + yb) * sg;
}

// ---------------- host ----------------
extern "C" void kernel_launch(void* const* d_in, const int* in_sizes, int n_in,
                              void* d_out, int out_size) {
    const float* x        = (const float*)d_in[0];
    const float* patch_w  = (const float*)d_in[1];
    const float* patch_b  = (const float*)d_in[2];
    const float* pos      = (const float*)d_in[3];
    const float* temp     = (const float*)d_in[4];
    const float* in_proj  = (const float*)d_in[5];
    const float* conv_w   = (const float*)d_in[6];
    const float* conv_b   = (const float*)d_in[7];
    const float* xproj_w  = (const float*)d_in[8];
    const float* dt_w     = (const float*)d_in[9];
    const float* dt_b     = (const float*)d_in[10];
    const float* A_log    = (const float*)d_in[11];
    const float* Dp       = (const float*)d_in[12];
    const float* conv_wb  = (const float*)d_in[13];
    const float* conv_bb  = (const float*)d_in[14];
    const float* xproj_wb = (const float*)d_in[15];
    const float* dt_wb    = (const float*)d_in[16];
    const float* dt_bb    = (const float*)d_in[17];
    const float* A_logb   = (const float*)d_in[18];
    const float* Dpb      = (const float*)d_in[19];
    const float* out_proj = (const float*)d_in[20];
    const float* norm_w   = (const float*)d_in[21];
    const float* norm_f   = (const float*)d_in[22];

    float *p_patches, *p_hidden, *p_resid, *p_norm, *p_xz, *p_xc, *p_dt,
          *p_xpart, *p_xdbl, *p_ycomb;
    cudaGetSymbolAddress((void**)&p_patches, g_patches);
    cudaGetSymbolAddress((void**)&p_hidden,  g_hidden);
    cudaGetSymbolAddress((void**)&p_resid,   g_resid);
    cudaGetSymbolAddress((void**)&p_norm,    g_norm);
    cudaGetSymbolAddress((void**)&p_xz,      g_xz);
    cudaGetSymbolAddress((void**)&p_xc,      g_xc);
    cudaGetSymbolAddress((void**)&p_dt,      g_dt);
    cudaGetSymbolAddress((void**)&p_xpart,   g_xpart);
    cudaGetSymbolAddress((void**)&p_xdbl,    g_xdbl);
    cudaGetSymbolAddress((void**)&p_ycomb,   g_ycomb);

    k_patch_gather<<<(NPATCH * PKDIM + 255) / 256, 256>>>(x);
    k_zero<<<(LTOT * DM + 255) / 256, 256>>>(p_resid, LTOT * DM);
    // patch embed: hidden[bl, m] = patch_w[m,:] . patches[bl,:] + bias + pos + temp
    k_gemm<128, 1, 1><<<dim3(49, 3, 1), 256>>>(
        patch_w, p_patches, p_hidden, DM, LTOT, PKDIM,
        PKDIM, PKDIM, DM, 0, 0, 0, patch_b, pos, temp);

    for (int ly = 0; ly < DEPTH; ly++) {
        k_prenorm<<<LTOT, 128>>>(norm_w + ly * DM);

        // in_proj: xz[e, bl] = W[e,:] . norm[bl,:]
        k_gemm<128, 1, 0><<<dim3(49, 12, 1), 256>>>(
            in_proj + (long)ly * 2 * DI * DM, p_norm, p_xz,
            2 * DI, LTOT, DM, DM, DM, LTOT, 0, 0, 0,
            nullptr, nullptr, nullptr);

        {
            dim3 g((DI * LTOT + 255) / 256, 2);
            k_conv<<<g, 256>>>(conv_w + (long)ly * DI * 4, conv_b + (long)ly * DI,
                               conv_wb + (long)ly * DI * 4, conv_bb + (long)ly * DI);
        }

        for (int dir = 0; dir < 2; dir++) {
            const float* xpw = (dir ? xproj_wb : xproj_w) + (long)ly * 56 * DI;
            // split-K=4 (slices of 192)
            k_gemm<64, 0, 0><<<dim3(49, 1, 4), 256>>>(
                xpw, p_xc + (long)dir * DI * LTOT, p_xpart + (long)dir * 4 * 56 * LTOT,
                56, LTOT, 192, DI, LTOT, LTOT,
                192, (long)192 * LTOT, (long)56 * LTOT,
                nullptr, nullptr, nullptr);
        }
        k_xpred<<<(2 * 56 * LTOT + 255) / 256, 256>>>();

        for (int dir = 0; dir < 2; dir++) {
            const float* dw = (dir ? dt_wb : dt_w) + (long)ly * DI * DTR;
            const float* db = (dir ? dt_bb : dt_b) + (long)ly * DI;
            k_gemm<128, 0, 2><<<dim3(49, 6, 1), 256>>>(
                dw, p_xdbl + (long)dir * 56 * LTOT, p_dt + (long)dir * DI * LTOT,
                DI, LTOT, DTR, DTR, LTOT, LTOT, 0, 0, 0,
                db, nullptr, nullptr);
        }

        k_bc_t<<<(2 * BATCHSZ * LSEQ * DST + 255) / 256, 256>>>();
        k_scan<<<192, 256>>>(A_log + (long)ly * DI * DST, A_logb + (long)ly * DI * DST);
        k_combine<<<(DI * LTOT + 255) / 256, 256>>>(Dp + (long)ly * DI, Dpb + (long)ly * DI);

        // out_proj: hidden[bl, o] = W[o,:] . ycomb[:, bl]
        k_gemm<128, 0, 3><<<dim3(49, 3, 1), 256>>>(
            out_proj + (long)ly * DM * DI, p_ycomb, p_hidden,
            DM, LTOT, DI, DI, LTOT, DM, 0, 0, 0,
            nullptr, nullptr, nullptr);
    }

    k_final<<<LTOT, 128>>>(norm_f, (float*)d_out);
}

// round 6
// speedup vs baseline: 1.7743x; 1.1396x over previous
#include <cuda_runtime.h>

#define BATCHSZ 2
#define DM      384
#define DI      768
#define LSEQ    1568
#define LTOT    3136      // BATCH * LSEQ
#define DTR     24
#define DST     16
#define DEPTH   24
#define NPATCH  3136
#define PKDIM   768

// ---------------- scratch ----------------
__device__ float g_patches[NPATCH * PKDIM];
__device__ float g_hidden [LTOT * DM];
__device__ float g_resid  [LTOT * DM];
__device__ float g_norm   [LTOT * DM];
__device__ float g_xz     [2 * DI * LTOT];          // (e, bl)
__device__ float g_xc     [2 * DI * LTOT];          // (dir*DI+d, bl)
__device__ float g_dt     [2 * DI * LTOT];
__device__ float g_xpart  [2 * 4 * 56 * LTOT];      // split-K partials
__device__ float g_xdbl   [2 * 56 * LTOT];
__device__ float g_btr    [2 * BATCHSZ * LSEQ * DST];
__device__ float g_ctr    [2 * BATCHSZ * LSEQ * DST];
__device__ float g_ys     [2 * DI * LTOT];
__device__ float g_ycomb  [DI * LTOT];

__global__ void k_zero(float* p, int n) {
    int i = blockIdx.x * blockDim.x + threadIdx.x;
    if (i < n) p[i] = 0.f;
}

__global__ void k_patch_gather(const float* __restrict__ x) {
    int idx = blockIdx.x * blockDim.x + threadIdx.x;
    if (idx >= NPATCH * PKDIM) return;
    int row = idx / PKDIM, c = idx % PKDIM;
    int b = row / 1568; int rem = row % 1568; int t = rem / 196; int n = rem % 196;
    int gy = n / 14, gx = n % 14;
    int ch = c / 256; int r = c % 256; int py = r / 16, px = r % 16;
    g_patches[idx] = x[(((long)(b * 3 + ch) * 8 + t) * 224 + gy * 16 + py) * 224 + gx * 16 + px];
}

// res += hidden; norm = rmsnorm(res)*nw
__global__ void k_prenorm(const float* __restrict__ nw) {
    int base = blockIdx.x * DM;
    __shared__ float red[4];
    float v[3]; float ss = 0.f;
#pragma unroll
    for (int i = 0; i < 3; i++) {
        int c = threadIdx.x + i * 128;
        float t = g_resid[base + c] + g_hidden[base + c];
        g_resid[base + c] = t; v[i] = t; ss += t * t;
    }
#pragma unroll
    for (int o = 16; o; o >>= 1) ss += __shfl_xor_sync(0xffffffffu, ss, o);
    if ((threadIdx.x & 31) == 0) red[threadIdx.x >> 5] = ss;
    __syncthreads();
    float r = rsqrtf((red[0] + red[1] + red[2] + red[3]) * (1.f / DM) + 1e-5f);
#pragma unroll
    for (int i = 0; i < 3; i++) {
        int c = threadIdx.x + i * 128;
        g_norm[base + c] = v[i] * r * nw[c];
    }
}

__global__ void k_final(const float* __restrict__ nf, float* __restrict__ out) {
    int base = blockIdx.x * DM;
    __shared__ float red[4];
    float v[3]; float ss = 0.f;
#pragma unroll
    for (int i = 0; i < 3; i++) {
        int c = threadIdx.x + i * 128;
        float t = g_resid[base + c] + g_hidden[base + c];
        v[i] = t; ss += t * t;
    }
#pragma unroll
    for (int o = 16; o; o >>= 1) ss += __shfl_xor_sync(0xffffffffu, ss, o);
    if ((threadIdx.x & 31) == 0) red[threadIdx.x >> 5] = ss;
    __syncthreads();
    float r = rsqrtf((red[0] + red[1] + red[2] + red[3]) * (1.f / DM) + 1e-5f);
#pragma unroll
    for (int i = 0; i < 3; i++) {
        int c = threadIdx.x + i * 128;
        out[base + c] = v[i] * r * nf[c];
    }
}

// =========================================================================
// bf16x2 tensor-core GEMM (error-compensated: C = Ah*Bh + Ah*Bl + Al*Bh)
// Tile 128x64, BK=32 fp32. 256 threads = 8 warps (4m x 2n), warp tile 32x32.
// A: [M,K] fp32 row-major.  BLAY=1: B [N,K];  BLAY=0: B [K,N].
// EPI 0: C[m*ldc+n]
// EPI 1: transposed C[n*ldc+m] + patch adds (e0 bias[m], e1 pos, e2 temp)
// EPI 3: transposed C[n*ldc+m]
// Requires M%128==0, N%64==0, K%32==0.
// =========================================================================
__device__ __forceinline__ unsigned bf16rn(float x) {
    unsigned u = __float_as_uint(x);
    return (u + 0x7FFFu + ((u >> 16) & 1u)) >> 16;
}
__device__ __forceinline__ void ldsm4(unsigned* r, const void* p) {
    unsigned a = (unsigned)__cvta_generic_to_shared(p);
    asm volatile("ldmatrix.sync.aligned.m8n8.x4.shared.b16 {%0,%1,%2,%3},[%4];"
                 : "=r"(r[0]), "=r"(r[1]), "=r"(r[2]), "=r"(r[3]) : "r"(a));
}
__device__ __forceinline__ void ldsm4t(unsigned* r, const void* p) {
    unsigned a = (unsigned)__cvta_generic_to_shared(p);
    asm volatile("ldmatrix.sync.aligned.m8n8.x4.trans.shared.b16 {%0,%1,%2,%3},[%4];"
                 : "=r"(r[0]), "=r"(r[1]), "=r"(r[2]), "=r"(r[3]) : "r"(a));
}
__device__ __forceinline__ void mma16816(float* c, const unsigned* a, const unsigned* b) {
    asm volatile("mma.sync.aligned.m16n8k16.row.col.f32.bf16.bf16.f32 "
                 "{%0,%1,%2,%3},{%4,%5,%6,%7},{%8,%9},{%0,%1,%2,%3};"
                 : "+f"(c[0]), "+f"(c[1]), "+f"(c[2]), "+f"(c[3])
                 : "r"(a[0]), "r"(a[1]), "r"(a[2]), "r"(a[3]), "r"(b[0]), "r"(b[1]));
}

template<int EPI, int BLAY>
__global__ void __launch_bounds__(256)
k_mma(const float* __restrict__ A, const float* __restrict__ B,
      float* __restrict__ C, int M, int N, int K,
      int lda, int ldb, int ldc,
      const float* __restrict__ e0, const float* __restrict__ e1,
      const float* __restrict__ e2)
{
    constexpr int BR = BLAY ? 64 : 32;   // B smem rows
    constexpr int BC = BLAY ? 40 : 72;   // padded cols (bf16): 80B / 144B strides
    __shared__ unsigned short sAh[128][40], sAl[128][40];
    __shared__ unsigned short sBh[BR][BC], sBl[BR][BC];

    const int tid = threadIdx.x, lane = tid & 31;
    const int w = tid >> 5, wm = w >> 1, wn = w & 1;
    const int m0 = blockIdx.y * 128, n0 = blockIdx.x * 64;

    // staging maps
    const int a_row = tid >> 1, a_kq0 = (tid & 1) * 4;        // A: 4 float4/thread
    const int b1_row = tid >> 2, b1_kq0 = (tid & 3) * 2;      // B[N][K]: 2 f4/thread
    const int b0_row = tid >> 3, b0_nq0 = (tid & 7) * 2;      // B[K][N]: 2 f4/thread

    float4 pa[4], pb[2];
    auto fetch = [&](int k0) {
#pragma unroll
        for (int i = 0; i < 4; i++)
            pa[i] = *(const float4*)(A + (long)(m0 + a_row) * lda + k0 + (a_kq0 + i) * 4);
#pragma unroll
        for (int i = 0; i < 2; i++) {
            if (BLAY)
                pb[i] = *(const float4*)(B + (long)(n0 + b1_row) * ldb + k0 + (b1_kq0 + i) * 4);
            else
                pb[i] = *(const float4*)(B + (long)(k0 + b0_row) * ldb + n0 + (b0_nq0 + i) * 4);
        }
    };
    auto cv4 = [&](float4 v, unsigned short* base_h, unsigned short* base_l) {
        float xs[4] = {v.x, v.y, v.z, v.w};
        unsigned h[4], l[4];
#pragma unroll
        for (int e = 0; e < 4; e++) {
            h[e] = bf16rn(xs[e]);
            float hf = __uint_as_float(h[e] << 16);
            l[e] = bf16rn(xs[e] - hf);
        }
        *(uint2*)base_h = make_uint2(h[0] | (h[1] << 16), h[2] | (h[3] << 16));
        *(uint2*)base_l = make_uint2(l[0] | (l[1] << 16), l[2] | (l[3] << 16));
    };
    auto stage = [&]() {
#pragma unroll
        for (int i = 0; i < 4; i++)
            cv4(pa[i], &sAh[a_row][(a_kq0 + i) * 4], &sAl[a_row][(a_kq0 + i) * 4]);
#pragma unroll
        for (int i = 0; i < 2; i++) {
            if (BLAY) cv4(pb[i], &sBh[b1_row][(b1_kq0 + i) * 4], &sBl[b1_row][(b1_kq0 + i) * 4]);
            else      cv4(pb[i], &sBh[b0_row][(b0_nq0 + i) * 4], &sBl[b0_row][(b0_nq0 + i) * 4]);
        }
    };

    float acc[2][4][4];
#pragma unroll
    for (int i = 0; i < 2; i++)
#pragma unroll
        for (int j = 0; j < 4; j++)
#pragma unroll
            for (int q = 0; q < 4; q++) acc[i][j][q] = 0.f;

    // ldmatrix lane-address components
    const int af_r = lane & 15, af_k = (lane >> 4) * 8;                     // A frags
    const int b1_r = ((lane >> 4) << 3) + (lane & 7), b1_k = ((lane >> 3) & 1) * 8;  // B[N][K]
    const int b0_k = ((lane >> 3) & 1) * 8 + (lane & 7), b0_n = (lane >> 4) * 8;     // B[K][N]

    const int nst = K >> 5;
    fetch(0);
    for (int t = 0; t < nst; t++) {
        stage();
        __syncthreads();
        if (t + 1 < nst) fetch((t + 1) << 5);
#pragma unroll
        for (int ks = 0; ks < 2; ks++) {
            const int kb = ks * 16;
            unsigned ah[2][4], al[2][4], bh[4][2], bl[4][2];
#pragma unroll
            for (int mf = 0; mf < 2; mf++) {
                ldsm4(ah[mf], &sAh[wm * 32 + mf * 16 + af_r][kb + af_k]);
                ldsm4(al[mf], &sAl[wm * 32 + mf * 16 + af_r][kb + af_k]);
            }
#pragma unroll
            for (int g = 0; g < 2; g++) {
                unsigned th[4], tl[4];
                if (BLAY) {
                    ldsm4(th, &sBh[wn * 32 + g * 16 + b1_r][kb + b1_k]);
                    ldsm4(tl, &sBl[wn * 32 + g * 16 + b1_r][kb + b1_k]);
                } else {
                    ldsm4t(th, &sBh[kb + b0_k][wn * 32 + g * 16 + b0_n]);
                    ldsm4t(tl, &sBl[kb + b0_k][wn * 32 + g * 16 + b0_n]);
                }
                bh[g * 2][0] = th[0]; bh[g * 2][1] = th[1];
                bh[g * 2 + 1][0] = th[2]; bh[g * 2 + 1][1] = th[3];
                bl[g * 2][0] = tl[0]; bl[g * 2][1] = tl[1];
                bl[g * 2 + 1][0] = tl[2]; bl[g * 2 + 1][1] = tl[3];
            }
#pragma unroll
            for (int mf = 0; mf < 2; mf++)
#pragma unroll
                for (int nf = 0; nf < 4; nf++) {
                    mma16816(acc[mf][nf], ah[mf], bh[nf]);
                    mma16816(acc[mf][nf], ah[mf], bl[nf]);
                    mma16816(acc[mf][nf], al[mf], bh[nf]);
                }
        }
        __syncthreads();
    }

    // epilogue
    const int r = lane >> 2, c2 = (lane & 3) * 2;
#pragma unroll
    for (int mf = 0; mf < 2; mf++)
#pragma unroll
        for (int nf = 0; nf < 4; nf++) {
            int m = m0 + wm * 32 + mf * 16 + r;
            int n = n0 + wn * 32 + nf * 8 + c2;
            float* cc = acc[mf][nf];
            if (EPI == 0) {
                *(float2*)(C + (long)m * ldc + n) = make_float2(cc[0], cc[1]);
                *(float2*)(C + (long)(m + 8) * ldc + n) = make_float2(cc[2], cc[3]);
            } else {
#pragma unroll
                for (int q = 0; q < 4; q++) {
                    int mm = m + (q >> 1) * 8;
                    int nn = n + (q & 1);
                    float v = cc[q];
                    if (EPI == 1)
                        v += e0[mm] + e1[(nn % 196) * DM + mm] + e2[((nn / 196) & 7) * DM + mm];
                    C[(long)nn * ldc + mm] = v;
                }
            }
        }
}

// ---------------- FFMA GEMM (for xproj / dt): BMx64x16, 256 thr, TMx4/thread ----
// A: [M,K] row-major. B: TB=1 -> [N,K]; TB=0 -> [K,N].
// EPI 0: plain   EPI 2: softplus(v + e0[m])
template<int BM, int TB, int EPI>
__global__ void __launch_bounds__(256)
k_gemm(const float* __restrict__ A, const float* __restrict__ B,
       float* __restrict__ C, int M, int N, int K,
       int lda, int ldb, int ldc,
       long zA, long zB, long zC,
       const float* __restrict__ e0)
{
    constexpr int TM = BM / 16;
    constexpr int AV = BM / 64;
    __shared__ float As[2][16][BM + 4];
    __shared__ float Bs[2][16][68];
    A += blockIdx.z * zA; B += blockIdx.z * zB; C += blockIdx.z * zC;
    const int m0 = blockIdx.y * BM, n0 = blockIdx.x * 64;
    const int tid = threadIdx.x, tx = tid & 15, ty = tid >> 4;
    const int arow = tid >> 2, akc = (tid & 3) * 4;
    const int bkr = tid >> 4, bnc = (tid & 15) * 4;

    float4 pa[AV], pb;
    auto fetch = [&](int k0) {
#pragma unroll
        for (int i = 0; i < AV; i++) {
            int row = arow + i * 64;
            int m = m0 + row, k = k0 + akc;
            pa[i] = (m < M && k < K) ? *(const float4*)(A + (long)m * lda + k)
                                     : make_float4(0.f, 0.f, 0.f, 0.f);
        }
        if (TB) {
            int n = n0 + arow, k = k0 + akc;
            pb = (k < K) ? *(const float4*)(B + (long)n * ldb + k)
                         : make_float4(0.f, 0.f, 0.f, 0.f);
        } else {
            int k = k0 + bkr;
            pb = (k < K) ? *(const float4*)(B + (long)k * ldb + n0 + bnc)
                         : make_float4(0.f, 0.f, 0.f, 0.f);
        }
    };
    auto stage = [&](int s) {
#pragma unroll
        for (int i = 0; i < AV; i++) {
            int row = arow + i * 64;
            As[s][akc + 0][row] = pa[i].x; As[s][akc + 1][row] = pa[i].y;
            As[s][akc + 2][row] = pa[i].z; As[s][akc + 3][row] = pa[i].w;
        }
        if (TB) {
            Bs[s][akc + 0][arow] = pb.x; Bs[s][akc + 1][arow] = pb.y;
            Bs[s][akc + 2][arow] = pb.z; Bs[s][akc + 3][arow] = pb.w;
        } else {
            *(float4*)&Bs[s][bkr][bnc] = pb;
        }
    };

    float acc[TM][4];
#pragma unroll
    for (int i = 0; i < TM; i++)
#pragma unroll
        for (int j = 0; j < 4; j++) acc[i][j] = 0.f;

    const int nt = (K + 15) >> 4;
    fetch(0); stage(0); __syncthreads();
    for (int t = 0; t < nt; t++) {
        int cur = t & 1;
        if (t + 1 < nt) fetch((t + 1) << 4);
#pragma unroll
        for (int k = 0; k < 16; k++) {
            float a[TM], b[4];
#pragma unroll
            for (int i = 0; i < TM / 4; i++)
                *(float4*)&a[4 * i] = *(const float4*)&As[cur][k][ty * TM + 4 * i];
            *(float4*)&b[0] = *(const float4*)&Bs[cur][k][tx * 4];
#pragma unroll
            for (int i = 0; i < TM; i++)
#pragma unroll
                for (int j = 0; j < 4; j++)
                    acc[i][j] = fmaf(a[i], b[j], acc[i][j]);
        }
        if (t + 1 < nt) stage(cur ^ 1);
        __syncthreads();
    }

#pragma unroll
    for (int i = 0; i < TM; i++) {
        int m = m0 + ty * TM + i;
        if (m >= M) continue;
        float4 v = *(float4*)&acc[i][0];
        if (EPI == 2) {
            float bb = e0[m];
            v.x += bb; v.y += bb; v.z += bb; v.w += bb;
            v.x = (v.x > 20.f) ? v.x : log1pf(__expf(v.x));
            v.y = (v.y > 20.f) ? v.y : log1pf(__expf(v.y));
            v.z = (v.z > 20.f) ? v.z : log1pf(__expf(v.z));
            v.w = (v.w > 20.f) ? v.w : log1pf(__expf(v.w));
        }
        *(float4*)(C + (long)m * ldc + n0 + tx * 4) = v;
    }
}

// reduce split-K partials
__global__ void k_xpred() {
    int idx = blockIdx.x * blockDim.x + threadIdx.x;
    if (idx >= 2 * 56 * LTOT) return;
    int dir = idx / (56 * LTOT);
    int r = idx % (56 * LTOT);
    long base = (long)dir * 4 * 56 * LTOT + r;
    g_xdbl[idx] = g_xpart[base] + g_xpart[base + 56 * LTOT]
                + g_xpart[base + 2L * 56 * LTOT] + g_xpart[base + 3L * 56 * LTOT];
}

// causal depthwise conv (K=4) + silu; bwd reads flipped
__global__ void k_conv(const float* __restrict__ cwf, const float* __restrict__ cbf,
                       const float* __restrict__ cwb, const float* __restrict__ cbb) {
    int idx = blockIdx.x * blockDim.x + threadIdx.x;
    if (idx >= DI * LTOT) return;
    int dir = blockIdx.y;
    int d = idx / LTOT, bl = idx % LTOT;
    int b = bl / LSEQ, p = bl % LSEQ;
    const float* w = (dir ? cwb : cwf) + d * 4;
    float acc = (dir ? cbb : cbf)[d];
    const float* xi = g_xz + (long)d * LTOT + b * LSEQ;
#pragma unroll
    for (int k = 0; k < 4; k++) {
        int q = p - 3 + k;
        if (q >= 0) acc += w[k] * xi[dir ? (LSEQ - 1 - q) : q];
    }
    g_xc[((long)dir * DI + d) * LTOT + bl] = acc / (1.f + __expf(-acc));
}

// transpose B/C rows of xdbl into (dir,b,p,n)
__global__ void k_bc_t() {
    int idx = blockIdx.x * blockDim.x + threadIdx.x;
    if (idx >= 2 * BATCHSZ * LSEQ * DST) return;
    int n = idx & 15;
    int p = (idx >> 4) % LSEQ;
    int db = idx / (16 * LSEQ);
    int dir = db >> 1, b = db & 1;
    long src = (long)dir * 56 * LTOT + b * LSEQ + p;
    g_btr[idx] = g_xdbl[src + (long)(24 + n) * LTOT];
    g_ctr[idx] = g_xdbl[src + (long)(40 + n) * LTOT];
}

// selective scan
__global__ void k_scan(const float* __restrict__ Alog_f, const float* __restrict__ Alog_b) {
    int gid = blockIdx.x * (blockDim.x >> 4) + (threadIdx.x >> 4);
    if (gid >= 2 * BATCHSZ * DI) return;
    int n = threadIdx.x & 15;
    int dir = gid / (BATCHSZ * DI);
    int r = gid % (BATCHSZ * DI);
    int b = r / DI, d = r % DI;
    float acoef = -__expf((dir ? Alog_b : Alog_f)[d * DST + n]);
    long chan = ((long)dir * DI + d) * LTOT + b * LSEQ;
    const float* dtp = g_dt + chan;
    const float* xcp = g_xc + chan;
    float* ysp = g_ys + chan;
    long bc0 = ((long)dir * BATCHSZ + b) * LSEQ * (long)DST;
    const float* btp = g_btr + bc0;
    const float* ctp = g_ctr + bc0;
    float h = 0.f;
#pragma unroll 4
    for (int p = 0; p < LSEQ; p++) {
        float dtv = dtp[p], xcv = xcp[p];
        float a = __expf(dtv * acoef);
        float u = dtv * xcv * btp[p * DST + n];
        h = fmaf(a, h, u);
        float py = h * ctp[p * DST + n];
        py += __shfl_xor_sync(0xffffffffu, py, 1);
        py += __shfl_xor_sync(0xffffffffu, py, 2);
        py += __shfl_xor_sync(0xffffffffu, py, 4);
        py += __shfl_xor_sync(0xffffffffu, py, 8);
        if (n == 0) ysp[p] = py;
    }
}

__global__ void k_combine(const float* __restrict__ Dpf, const float* __restrict__ Dpb) {
    int idx = blockIdx.x * blockDim.x + threadIdx.x;
    if (idx >= DI * LTOT) return;
    int d = idx / LTOT, bl = idx % LTOT;
    int b = bl / LSEQ, l = bl % LSEQ;
    float z = g_xz[((long)DI + d) * LTOT + bl];
    float sg = z / (1.f + __expf(-z));
    long f = (long)d * LTOT + b * LSEQ;
    long bw = ((long)DI + d) * LTOT + b * LSEQ;
    int pb = LSEQ - 1 - l;
    float yf = g_ys[f + l] + Dpf[d] * g_xc[f + l];
    float yb = g_ys[bw + pb] + Dpb[d] * g_xc[bw + pb];
    g_ycomb[f + l] = (yf + yb) * sg;
}

// ---------------- host ----------------
extern "C" void kernel_launch(void* const* d_in, const int* in_sizes, int n_in,
                              void* d_out, int out_size) {
    const float* x        = (const float*)d_in[0];
    const float* patch_w  = (const float*)d_in[1];
    const float* patch_b  = (const float*)d_in[2];
    const float* pos      = (const float*)d_in[3];
    const float* temp     = (const float*)d_in[4];
    const float* in_proj  = (const float*)d_in[5];
    const float* conv_w   = (const float*)d_in[6];
    const float* conv_b   = (const float*)d_in[7];
    const float* xproj_w  = (const float*)d_in[8];
    const float* dt_w     = (const float*)d_in[9];
    const float* dt_b     = (const float*)d_in[10];
    const float* A_log    = (const float*)d_in[11];
    const float* Dp       = (const float*)d_in[12];
    const float* conv_wb  = (const float*)d_in[13];
    const float* conv_bb  = (const float*)d_in[14];
    const float* xproj_wb = (const float*)d_in[15];
    const float* dt_wb    = (const float*)d_in[16];
    const float* dt_bb    = (const float*)d_in[17];
    const float* A_logb   = (const float*)d_in[18];
    const float* Dpb      = (const float*)d_in[19];
    const float* out_proj = (const float*)d_in[20];
    const float* norm_w   = (const float*)d_in[21];
    const float* norm_f   = (const float*)d_in[22];

    float *p_patches, *p_hidden, *p_resid, *p_norm, *p_xz, *p_xc, *p_dt,
          *p_xpart, *p_xdbl, *p_ycomb;
    cudaGetSymbolAddress((void**)&p_patches, g_patches);
    cudaGetSymbolAddress((void**)&p_hidden,  g_hidden);
    cudaGetSymbolAddress((void**)&p_resid,   g_resid);
    cudaGetSymbolAddress((void**)&p_norm,    g_norm);
    cudaGetSymbolAddress((void**)&p_xz,      g_xz);
    cudaGetSymbolAddress((void**)&p_xc,      g_xc);
    cudaGetSymbolAddress((void**)&p_dt,      g_dt);
    cudaGetSymbolAddress((void**)&p_xpart,   g_xpart);
    cudaGetSymbolAddress((void**)&p_xdbl,    g_xdbl);
    cudaGetSymbolAddress((void**)&p_ycomb,   g_ycomb);

    k_patch_gather<<<(NPATCH * PKDIM + 255) / 256, 256>>>(x);
    k_zero<<<(LTOT * DM + 255) / 256, 256>>>(p_resid, LTOT * DM);
    // patch embed (tensor core): hidden[bl, m]
    k_mma<1, 1><<<dim3(49, 3), 256>>>(
        patch_w, p_patches, p_hidden, DM, LTOT, PKDIM,
        PKDIM, PKDIM, DM, patch_b, pos, temp);

    for (int ly = 0; ly < DEPTH; ly++) {
        k_prenorm<<<LTOT, 128>>>(norm_w + ly * DM);

        // in_proj (tensor core): xz[e, bl] = W[e,:] . norm[bl,:]
        k_mma<0, 1><<<dim3(49, 12), 256>>>(
            in_proj + (long)ly * 2 * DI * DM, p_norm, p_xz,
            2 * DI, LTOT, DM, DM, DM, LTOT, nullptr, nullptr, nullptr);

        {
            dim3 g((DI * LTOT + 255) / 256, 2);
            k_conv<<<g, 256>>>(conv_w + (long)ly * DI * 4, conv_b + (long)ly * DI,
                               conv_wb + (long)ly * DI * 4, conv_bb + (long)ly * DI);
        }

        for (int dir = 0; dir < 2; dir++) {
            const float* xpw = (dir ? xproj_wb : xproj_w) + (long)ly * 56 * DI;
            // split-K=4 (slices of 192)
            k_gemm<64, 0, 0><<<dim3(49, 1, 4), 256>>>(
                xpw, p_xc + (long)dir * DI * LTOT, p_xpart + (long)dir * 4 * 56 * LTOT,
                56, LTOT, 192, DI, LTOT, LTOT,
                192, (long)192 * LTOT, (long)56 * LTOT, nullptr);
        }
        k_xpred<<<(2 * 56 * LTOT + 255) / 256, 256>>>();

        for (int dir = 0; dir < 2; dir++) {
            const float* dw = (dir ? dt_wb : dt_w) + (long)ly * DI * DTR;
            const float* db = (dir ? dt_bb : dt_b) + (long)ly * DI;
            k_gemm<128, 0, 2><<<dim3(49, 6, 1), 256>>>(
                dw, p_xdbl + (long)dir * 56 * LTOT, p_dt + (long)dir * DI * LTOT,
                DI, LTOT, DTR, DTR, LTOT, LTOT, 0, 0, 0, db);
        }

        k_bc_t<<<(2 * BATCHSZ * LSEQ * DST + 255) / 256, 256>>>();
        k_scan<<<192, 256>>>(A_log + (long)ly * DI * DST, A_logb + (long)ly * DI * DST);
        k_combine<<<(DI * LTOT + 255) / 256, 256>>>(Dp + (long)ly * DI, Dpb + (long)ly * DI);

        // out_proj (tensor core, transposed store): hidden[bl, o]
        k_mma<3, 0><<<dim3(49, 3), 256>>>(
            out_proj + (long)ly * DM * DI, p_ycomb, p_hidden,
            DM, LTOT, DI, DI, LTOT, DM, nullptr, nullptr, nullptr);
    }

    k_final<<<LTOT, 128>>>(norm_f, (float*)d_out);
}